// round 3
// baseline (speedup 1.0000x reference)
#include <cuda_runtime.h>
#include <math.h>

#define DEVI __device__ __forceinline__

__device__ float g_mu[16384];
__device__ float g_rstd[16384];
__device__ float g_q[2048 * 4096];     // [ng][o][pos]
__device__ float g_vs[2048 * 8];       // [ng][j][x,y]
__device__ float g_k[2048 * 256];      // [ng][j][o]
__device__ float g_v[2048 * 256];
__device__ float g_bias[2048 * 256];   // [ng][qi*4+j]
__device__ float g_att[512 * 16384];   // [c][n*64+qi]

DEVI unsigned f2tf(float x) { unsigned u; asm("cvt.rna.tf32.f32 %0, %1;" : "=r"(u) : "f"(x)); return u; }
DEVI void mma8(float* c, const unsigned* a, unsigned b0, unsigned b1) {
    asm("mma.sync.aligned.m16n8k8.row.col.f32.tf32.tf32.f32 "
        "{%0,%1,%2,%3}, {%4,%5,%6,%7}, {%8,%9}, {%0,%1,%2,%3};"
        : "+f"(c[0]), "+f"(c[1]), "+f"(c[2]), "+f"(c[3])
        : "r"(a[0]), "r"(a[1]), "r"(a[2]), "r"(a[3]), "r"(b0), "r"(b1));
}

// ---------------- K1: LayerNorm stats ----------------
__global__ void __launch_bounds__(256) k_ln(const float* __restrict__ x) {
    int b = blockIdx.x >> 3, rp = blockIdx.x & 7;
    int t = threadIdx.x, pl = t & 31, w = t >> 5;
    const float* px = x + b * 262144 + rp * 32 + pl;
    float s = 0.f, q = 0.f;
    for (int c = w; c < 1024; c += 8) { float v = px[c * 256]; s += v; q += v * v; }
    __shared__ float rs[8][32], rq[8][32];
    rs[w][pl] = s; rq[w][pl] = q;
    __syncthreads();
    if (t < 32) {
        float S = 0.f, Q = 0.f;
        #pragma unroll
        for (int i = 0; i < 8; i++) { S += rs[i][t]; Q += rq[i][t]; }
        float mu = S * (1.f / 1024.f);
        float var = Q * (1.f / 1024.f) - mu * mu;
        g_mu[b * 256 + rp * 32 + t] = mu;
        g_rstd[b * 256 + rp * 32 + t] = rsqrtf(var + 1e-6f);
    }
}

// ---------------- K2: Q projection ----------------
__global__ void __launch_bounds__(256) k_qproj(
    const float* __restrict__ x, const float* __restrict__ lg,
    const float* __restrict__ lb, const float* __restrict__ wq) {
    __shared__ float xns[128][64];
    int ng = blockIdx.x, n = ng >> 3, g = ng & 7;
    int b = n & 63, quad = n >> 6, qh = quad >> 1, qw = quad & 1;
    int t = threadIdx.x;
    #pragma unroll 8
    for (int pass = 0; pass < 32; pass++) {
        int e = t + (pass << 8);
        int pos = e & 63, i = e >> 6;
        int y = (qh << 3) + (pos >> 3), xx = (qw << 3) + (pos & 7);
        int cc = (g << 7) + i;
        float raw = x[(b * 1024 + cc) * 256 + y * 16 + xx];
        int mid = (b << 8) + y * 16 + xx;
        xns[i][pos] = (raw - g_mu[mid]) * g_rstd[mid] * __ldg(lg + cc) + __ldg(lb + cc);
    }
    __syncthreads();
    int o = t & 63, pb = t >> 6;
    const float* wr = wq + (g << 13) + (o << 7);
    float acc[16];
    #pragma unroll
    for (int u = 0; u < 16; u++) acc[u] = 0.f;
    #pragma unroll 2
    for (int i = 0; i < 128; i++) {
        float wv = __ldg(wr + i);
        const float4* xr = (const float4*)&xns[i][pb << 4];
        #pragma unroll
        for (int v4 = 0; v4 < 4; v4++) {
            float4 xv = xr[v4];
            acc[v4*4+0] += wv*xv.x; acc[v4*4+1] += wv*xv.y;
            acc[v4*4+2] += wv*xv.z; acc[v4*4+3] += wv*xv.w;
        }
    }
    float* op = g_q + ng * 4096 + (o << 6) + (pb << 4);
    #pragma unroll
    for (int v4 = 0; v4 < 4; v4++)
        ((float4*)op)[v4] = make_float4(acc[v4*4], acc[v4*4+1], acc[v4*4+2], acc[v4*4+3]);
}

// ---------------- K3: offset head ----------------
__global__ void __launch_bounds__(64) k_off(
    const float* __restrict__ w1c, const float* __restrict__ b1c,
    const float* __restrict__ w2c) {
    __shared__ float qs3[64][65];
    __shared__ float contrib[64][8];
    __shared__ float tmp8[8];
    int ng = blockIdx.x, t = threadIdx.x;
    for (int p = 0; p < 64; p++) qs3[p][t] = g_q[ng * 4096 + p * 64 + t];
    float wr[36];
    #pragma unroll
    for (int u = 0; u < 36; u++) wr[u] = w1c[t * 36 + u];
    float bias = b1c[t], w2a = w2c[t], w2b = w2c[64 + t];
    __syncthreads();
    #pragma unroll
    for (int sy = 0; sy < 2; sy++)
    #pragma unroll
    for (int sx = 0; sx < 2; sx++) {
        float s = bias;
        #pragma unroll
        for (int ky = 0; ky < 6; ky++) {
            int iy = sy * 4 - 1 + ky;
            if (iy < 0 || iy > 7) continue;
            #pragma unroll
            for (int kx = 0; kx < 6; kx++) {
                int ix = sx * 4 - 1 + kx;
                if (ix < 0 || ix > 7) continue;
                s += wr[ky * 6 + kx] * qs3[t][iy * 8 + ix];
            }
        }
        float gl = 0.5f * s * (1.f + erff(s * 0.70710678118654752f));
        contrib[t][(sy * 2 + sx) * 2 + 0] = gl * w2a;
        contrib[t][(sy * 2 + sx) * 2 + 1] = gl * w2b;
    }
    __syncthreads();
    if (t < 8) {
        float s = 0.f;
        for (int cc = 0; cc < 64; cc++) s += contrib[cc][t];
        tmp8[t] = 4.f * tanhf(s);
    }
    __syncthreads();
    if (t < 4) {
        int sy = t >> 1, sx = t & 1;
        g_vs[ng * 8 + t * 2 + 0] = 2.f * ((float)sx + tmp8[t * 2 + 0]) - 1.f;
        g_vs[ng * 8 + t * 2 + 1] = 2.f * ((float)sy + tmp8[t * 2 + 1]) - 1.f;
    }
}

// ---------------- K4: bilinear KV gather + K/V proj ----------------
__global__ void __launch_bounds__(128) k_kv(
    const float* __restrict__ x, const float* __restrict__ lg,
    const float* __restrict__ lb, const float* __restrict__ wk,
    const float* __restrict__ wv) {
    __shared__ float kvs[128][5];
    int ng = blockIdx.x, n = ng >> 3, g = ng & 7;
    int b = n & 63, quad = n >> 6, qh = quad >> 1, qw = quad & 1;
    int t = threadIdx.x;
    int cc = (g << 7) + t;
    float lgv = __ldg(lg + cc), lbv = __ldg(lb + cc);
    const float* xb = x + (b * 1024 + cc) * 256;
    #pragma unroll
    for (int j = 0; j < 4; j++) {
        float vx = g_vs[ng * 8 + j * 2 + 0], vy = g_vs[ng * 8 + j * 2 + 1];
        float fx = ((vx + 1.f) * 8.f - 1.f) * 0.5f;
        float fy = ((vy + 1.f) * 8.f - 1.f) * 0.5f;
        float x0 = floorf(fx), y0 = floorf(fy);
        float wx1 = fx - x0, wy1 = fy - y0;
        float acc = 0.f;
        #pragma unroll
        for (int dy = 0; dy < 2; dy++)
        #pragma unroll
        for (int dx = 0; dx < 2; dx++) {
            float X = x0 + dx, Y = y0 + dy;
            if (X >= 0.f && X <= 7.f && Y >= 0.f && Y <= 7.f) {
                float wgt = (dx ? wx1 : 1.f - wx1) * (dy ? wy1 : 1.f - wy1);
                int gy = (qh << 3) + (int)Y, gx = (qw << 3) + (int)X;
                float raw = __ldg(xb + gy * 16 + gx);
                int mid = (b << 8) + gy * 16 + gx;
                acc += wgt * ((raw - g_mu[mid]) * g_rstd[mid] * lgv + lbv);
            }
        }
        kvs[t][j] = acc;
    }
    __syncthreads();
    int o = t & 63, which = t >> 6;
    const float* wb = (which ? wv : wk) + (g << 13) + (o << 7);
    float a0 = 0.f, a1 = 0.f, a2 = 0.f, a3 = 0.f;
    #pragma unroll 4
    for (int i = 0; i < 128; i++) {
        float wt = __ldg(wb + i);
        a0 += wt * kvs[i][0]; a1 += wt * kvs[i][1];
        a2 += wt * kvs[i][2]; a3 += wt * kvs[i][3];
    }
    float* dst = (which ? g_v : g_k) + (ng << 8) + o;
    dst[0] = a0; dst[64] = a1; dst[128] = a2; dst[192] = a3;
}

// ---------------- K5: CPB MLP (tf32 mma layer2) ----------------
// block = one ng, 256 points (p = qi*4+j). np-groups of 32 points.
__global__ void __launch_bounds__(256) k_cpb(
    const float* __restrict__ w1, const float* __restrict__ b1,
    const float* __restrict__ w2, const float* __restrict__ b2,
    const float* __restrict__ w3, const float* __restrict__ b3) {
    __shared__ float H1s[256 * 40];      // [h][pt], stride 40 -> conflict-free frags
    __shared__ float bx[256], by[256];
    __shared__ float part[8][32];
    int ng = blockIdx.x, t = threadIdx.x;
    int lane = t & 31, w = t >> 5, gid = lane >> 2, tig = lane & 3;
    if (t < 256) {
        int qi = t >> 2, j = t & 3;
        float gqx = (2.f / 7.f) * (float)(qi & 7) - 1.f;
        float gqy = (2.f / 7.f) * (float)(qi >> 3) - 1.f;
        float px = gqx - g_vs[ng * 8 + j * 2 + 0];
        float py = gqy - g_vs[ng * 8 + j * 2 + 1];
        bx[t] = copysignf(log1pf(fabsf(px)), px);
        by[t] = copysignf(log1pf(fabsf(py)), py);
    }
    float w1x = w1[t], w1y = w1[256 + t], b1t = b1[t];
    int m0base = w * 32;
    for (int np = 0; np < 8; np++) {
        __syncthreads();
        #pragma unroll 4
        for (int idx = 0; idx < 32; idx++) {
            int p = np * 32 + idx;
            float h = fmaxf(w1x * bx[p] + w1y * by[p] + b1t, 0.f);
            H1s[t * 40 + idx] = __uint_as_float(f2tf(h));
        }
        __syncthreads();
        float c[2][4][4];
        #pragma unroll
        for (int mt = 0; mt < 2; mt++) {
            float ba = b2[m0base + mt * 16 + gid], bbv = b2[m0base + mt * 16 + gid + 8];
            #pragma unroll
            for (int nt = 0; nt < 4; nt++) { c[mt][nt][0] = ba; c[mt][nt][1] = ba; c[mt][nt][2] = bbv; c[mt][nt][3] = bbv; }
        }
        #pragma unroll 2
        for (int kc = 0; kc < 32; kc++) {
            int k0 = kc << 3;
            unsigned a[2][4];
            #pragma unroll
            for (int mt = 0; mt < 2; mt++) {
                int m = m0base + mt * 16 + gid;
                a[mt][0] = f2tf(__ldg(w2 + (k0 + tig) * 256 + m));
                a[mt][1] = f2tf(__ldg(w2 + (k0 + tig) * 256 + m + 8));
                a[mt][2] = f2tf(__ldg(w2 + (k0 + tig + 4) * 256 + m));
                a[mt][3] = f2tf(__ldg(w2 + (k0 + tig + 4) * 256 + m + 8));
            }
            #pragma unroll
            for (int nt = 0; nt < 4; nt++) {
                unsigned b0 = __float_as_uint(H1s[(k0 + tig) * 40 + nt * 8 + gid]);
                unsigned bv1 = __float_as_uint(H1s[(k0 + tig + 4) * 40 + nt * 8 + gid]);
                mma8(c[0][nt], a[0], b0, bv1);
                mma8(c[1][nt], a[1], b0, bv1);
            }
        }
        float colsum[8];
        #pragma unroll
        for (int nt = 0; nt < 4; nt++)
            #pragma unroll
            for (int q = 0; q < 2; q++) {
                float s = 0.f;
                #pragma unroll
                for (int mt = 0; mt < 2; mt++) {
                    int m = m0base + mt * 16 + gid;
                    s += __ldg(w3 + m) * fmaxf(c[mt][nt][q], 0.f);
                    s += __ldg(w3 + m + 8) * fmaxf(c[mt][nt][2 + q], 0.f);
                }
                colsum[nt * 2 + q] = s;
            }
        #pragma unroll
        for (int off = 4; off < 32; off <<= 1)
            #pragma unroll
            for (int i = 0; i < 8; i++) colsum[i] += __shfl_xor_sync(0xffffffffu, colsum[i], off);
        if (gid == 0) {
            #pragma unroll
            for (int i = 0; i < 8; i++) part[w][(i >> 1) * 8 + tig * 2 + (i & 1)] = colsum[i];
        }
        __syncthreads();
        if (t < 32) {
            float s = 0.f;
            #pragma unroll
            for (int wi = 0; wi < 8; wi++) s += part[wi][t];
            g_bias[ng * 256 + np * 32 + t] = s + b3[0];
        }
    }
}

// ---------------- K6: attention ----------------
__global__ void __launch_bounds__(256) k_att() {
    __shared__ float qs[64][65];
    __shared__ float ks4[4][65], vs4[4][65];
    __shared__ float att_s[64][5];
    int ng = blockIdx.x, n = ng >> 3, g = ng & 7;
    int t = threadIdx.x;
    #pragma unroll
    for (int p = 0; p < 16; p++) {
        int idx = t + (p << 8);
        qs[idx >> 6][idx & 63] = g_q[ng * 4096 + idx];
    }
    { int j = t >> 6, o = t & 63; ks4[j][o] = g_k[(ng << 8) + t]; vs4[j][o] = g_v[(ng << 8) + t]; }
    __syncthreads();
    int qi = t >> 2, j = t & 3;
    float s = 0.f;
    #pragma unroll 8
    for (int d = 0; d < 64; d++) s += qs[d][qi] * ks4[j][d];
    s = s * 0.125f + g_bias[(ng << 8) + t];
    float mx = fmaxf(s, __shfl_xor_sync(0xffffffffu, s, 1));
    mx = fmaxf(mx, __shfl_xor_sync(0xffffffffu, mx, 2));
    float e = __expf(s - mx);
    float sum = e;
    sum += __shfl_xor_sync(0xffffffffu, sum, 1);
    sum += __shfl_xor_sync(0xffffffffu, sum, 2);
    att_s[qi][j] = e / sum;
    __syncthreads();
    int qi2 = t & 63, dg = t >> 6;
    float a0 = att_s[qi2][0], a1 = att_s[qi2][1], a2 = att_s[qi2][2], a3 = att_s[qi2][3];
    #pragma unroll
    for (int dd = 0; dd < 16; dd++) {
        int d = (dg << 4) + dd;
        float r = a0 * vs4[0][d] + a1 * vs4[1][d] + a2 * vs4[2][d] + a3 * vs4[3][d];
        g_att[((g << 6) + d) * 16384 + (n << 6) + qi2] = r;
    }
}

// ---------------- K7: output projection, 3x tf32 split ----------------
__global__ void __launch_bounds__(256) k_out(
    const float* __restrict__ ow, const float* __restrict__ ob,
    float* __restrict__ out) {
    __shared__ float Ah[128 * 20], Al[128 * 20];
    __shared__ float Bh[16 * 136], Bl[16 * 136];
    int blk = blockIdx.x;
    int mb = (blk & 7) << 7, nb = (blk >> 3) << 7;
    int t = threadIdx.x, lane = t & 31, w = t >> 5;
    int gid = lane >> 2, tig = lane & 3;
    int mw = (w >> 2) << 6, nw = (w & 3) << 5;
    float c[4][4][4];
    #pragma unroll
    for (int mt = 0; mt < 4; mt++)
        #pragma unroll
        for (int nt = 0; nt < 4; nt++)
            #pragma unroll
            for (int q = 0; q < 4; q++) c[mt][nt][q] = 0.f;
    for (int ck = 0; ck < 32; ck++) {
        int k0 = ck << 4;
        #pragma unroll
        for (int sA = 0; sA < 2; sA++) {
            int r = (t >> 2) + sA * 64, kq = (t & 3) << 2;
            float4 av = *(const float4*)(ow + (mb + r) * 512 + k0 + kq);
            float vv[4] = {av.x, av.y, av.z, av.w};
            #pragma unroll
            for (int u = 0; u < 4; u++) {
                float h = __uint_as_float(f2tf(vv[u]));
                Ah[r * 20 + kq + u] = h;
                Al[r * 20 + kq + u] = __uint_as_float(f2tf(vv[u] - h));
            }
        }
        {
            int r = t >> 4, cq = (t & 15) << 3;
            const float4* gb = (const float4*)(g_att + (k0 + r) * 16384 + nb + cq);
            float4 b0 = gb[0], b1v = gb[1];
            float vv[8] = {b0.x, b0.y, b0.z, b0.w, b1v.x, b1v.y, b1v.z, b1v.w};
            #pragma unroll
            for (int u = 0; u < 8; u++) {
                float h = __uint_as_float(f2tf(vv[u]));
                Bh[r * 136 + cq + u] = h;
                Bl[r * 136 + cq + u] = __uint_as_float(f2tf(vv[u] - h));
            }
        }
        __syncthreads();
        #pragma unroll
        for (int ks = 0; ks < 2; ks++) {
            int kk = ks * 8 + tig;
            unsigned ah[4][4], al[4][4];
            #pragma unroll
            for (int mt = 0; mt < 4; mt++) {
                int m = mw + mt * 16 + gid;
                ah[mt][0] = __float_as_uint(Ah[m * 20 + kk]);
                ah[mt][1] = __float_as_uint(Ah[(m + 8) * 20 + kk]);
                ah[mt][2] = __float_as_uint(Ah[m * 20 + kk + 4]);
                ah[mt][3] = __float_as_uint(Ah[(m + 8) * 20 + kk + 4]);
                al[mt][0] = __float_as_uint(Al[m * 20 + kk]);
                al[mt][1] = __float_as_uint(Al[(m + 8) * 20 + kk]);
                al[mt][2] = __float_as_uint(Al[m * 20 + kk + 4]);
                al[mt][3] = __float_as_uint(Al[(m + 8) * 20 + kk + 4]);
            }
            #pragma unroll
            for (int nt = 0; nt < 4; nt++) {
                int col = nw + nt * 8 + gid;
                unsigned bh0 = __float_as_uint(Bh[kk * 136 + col]);
                unsigned bh1 = __float_as_uint(Bh[(kk + 4) * 136 + col]);
                unsigned bl0 = __float_as_uint(Bl[kk * 136 + col]);
                unsigned bl1 = __float_as_uint(Bl[(kk + 4) * 136 + col]);
                #pragma unroll
                for (int mt = 0; mt < 4; mt++) {
                    mma8(c[mt][nt], ah[mt], bh0, bh1);
                    mma8(c[mt][nt], al[mt], bh0, bh1);
                    mma8(c[mt][nt], ah[mt], bl0, bl1);
                }
            }
        }
        __syncthreads();
    }
    #pragma unroll
    for (int mt = 0; mt < 4; mt++)
        #pragma unroll
        for (int nt = 0; nt < 4; nt++)
            #pragma unroll
            for (int q = 0; q < 4; q++) {
                int o = mb + mw + mt * 16 + gid + ((q >> 1) << 3);
                int col = nb + nw + nt * 8 + tig * 2 + (q & 1);
                int n = col >> 6, qi = col & 63;
                int b = n & 63, quad = n >> 6;
                int y = ((quad >> 1) << 3) + (qi >> 3);
                int xx = ((quad & 1) << 3) + (qi & 7);
                out[((b * 1024 + o) * 16 + y) * 16 + xx] = c[mt][nt][q] + __ldg(ob + o);
            }
}

extern "C" void kernel_launch(void* const* d_in, const int* in_sizes, int n_in,
                              void* d_out, int out_size) {
    const float* x      = (const float*)d_in[0];
    const float* ln_g   = (const float*)d_in[1];
    const float* ln_b   = (const float*)d_in[2];
    const float* wq     = (const float*)d_in[3];
    const float* wk     = (const float*)d_in[4];
    const float* wv     = (const float*)d_in[5];
    const float* off_w1 = (const float*)d_in[6];
    const float* off_b1 = (const float*)d_in[7];
    const float* off_w2 = (const float*)d_in[8];
    const float* cpb_w1 = (const float*)d_in[9];
    const float* cpb_b1 = (const float*)d_in[10];
    const float* cpb_w2 = (const float*)d_in[11];
    const float* cpb_b2 = (const float*)d_in[12];
    const float* cpb_w3 = (const float*)d_in[13];
    const float* cpb_b3 = (const float*)d_in[14];
    const float* out_w  = (const float*)d_in[15];
    const float* out_b  = (const float*)d_in[16];
    float* out = (float*)d_out;
    k_ln<<<512, 256>>>(x);
    k_qproj<<<2048, 256>>>(x, ln_g, ln_b, wq);
    k_off<<<2048, 64>>>(off_w1, off_b1, off_w2);
    k_kv<<<2048, 128>>>(x, ln_g, ln_b, wk, wv);
    k_cpb<<<2048, 256>>>(cpb_w1, cpb_b1, cpb_w2, cpb_b2, cpb_w3, cpb_b3);
    k_att<<<2048, 256>>>();
    k_out<<<1024, 256>>>(out_w, out_b, out);
}

// round 4
// speedup vs baseline: 1.0556x; 1.0556x over previous
#include <cuda_runtime.h>
#include <math.h>

#define DEVI __device__ __forceinline__

__device__ float g_mu[16384];
__device__ float g_rstd[16384];
__device__ float g_q[2048 * 4096];     // [ng][o][pos]
__device__ float g_vs[2048 * 8];       // [ng][j][x,y]
__device__ float g_k[2048 * 256];      // [ng][j][o]
__device__ float g_v[2048 * 256];
__device__ float g_bias[2048 * 256];   // [ng][qi*4+j]
__device__ float g_att[512 * 16384];   // [c][n*64+qi]

DEVI unsigned f2tf(float x) { unsigned u; asm("cvt.rna.tf32.f32 %0, %1;" : "=r"(u) : "f"(x)); return u; }
DEVI void mma8(float* c, const unsigned* a, unsigned b0, unsigned b1) {
    asm("mma.sync.aligned.m16n8k8.row.col.f32.tf32.tf32.f32 "
        "{%0,%1,%2,%3}, {%4,%5,%6,%7}, {%8,%9}, {%0,%1,%2,%3};"
        : "+f"(c[0]), "+f"(c[1]), "+f"(c[2]), "+f"(c[3])
        : "r"(a[0]), "r"(a[1]), "r"(a[2]), "r"(a[3]), "r"(b0), "r"(b1));
}

// ---------------- K1: LayerNorm stats ----------------
__global__ void __launch_bounds__(256) k_ln(const float* __restrict__ x) {
    int b = blockIdx.x >> 3, rp = blockIdx.x & 7;
    int t = threadIdx.x, pl = t & 31, w = t >> 5;
    const float* px = x + b * 262144 + rp * 32 + pl;
    float s = 0.f, q = 0.f;
    for (int c = w; c < 1024; c += 8) { float v = px[c * 256]; s += v; q += v * v; }
    __shared__ float rs[8][32], rq[8][32];
    rs[w][pl] = s; rq[w][pl] = q;
    __syncthreads();
    if (t < 32) {
        float S = 0.f, Q = 0.f;
        #pragma unroll
        for (int i = 0; i < 8; i++) { S += rs[i][t]; Q += rq[i][t]; }
        float mu = S * (1.f / 1024.f);
        float var = Q * (1.f / 1024.f) - mu * mu;
        g_mu[b * 256 + rp * 32 + t] = mu;
        g_rstd[b * 256 + rp * 32 + t] = rsqrtf(var + 1e-6f);
    }
}

// ---------------- K2: Q projection ----------------
__global__ void __launch_bounds__(256) k_qproj(
    const float* __restrict__ x, const float* __restrict__ lg,
    const float* __restrict__ lb, const float* __restrict__ wq) {
    __shared__ float xns[128][64];
    int ng = blockIdx.x, n = ng >> 3, g = ng & 7;
    int b = n & 63, quad = n >> 6, qh = quad >> 1, qw = quad & 1;
    int t = threadIdx.x;
    #pragma unroll 8
    for (int pass = 0; pass < 32; pass++) {
        int e = t + (pass << 8);
        int pos = e & 63, i = e >> 6;
        int y = (qh << 3) + (pos >> 3), xx = (qw << 3) + (pos & 7);
        int cc = (g << 7) + i;
        float raw = x[(b * 1024 + cc) * 256 + y * 16 + xx];
        int mid = (b << 8) + y * 16 + xx;
        xns[i][pos] = (raw - g_mu[mid]) * g_rstd[mid] * __ldg(lg + cc) + __ldg(lb + cc);
    }
    __syncthreads();
    int o = t & 63, pb = t >> 6;
    const float* wr = wq + (g << 13) + (o << 7);
    float acc[16];
    #pragma unroll
    for (int u = 0; u < 16; u++) acc[u] = 0.f;
    #pragma unroll 2
    for (int i = 0; i < 128; i++) {
        float wv = __ldg(wr + i);
        const float4* xr = (const float4*)&xns[i][pb << 4];
        #pragma unroll
        for (int v4 = 0; v4 < 4; v4++) {
            float4 xv = xr[v4];
            acc[v4*4+0] += wv*xv.x; acc[v4*4+1] += wv*xv.y;
            acc[v4*4+2] += wv*xv.z; acc[v4*4+3] += wv*xv.w;
        }
    }
    float* op = g_q + ng * 4096 + (o << 6) + (pb << 4);
    #pragma unroll
    for (int v4 = 0; v4 < 4; v4++)
        ((float4*)op)[v4] = make_float4(acc[v4*4], acc[v4*4+1], acc[v4*4+2], acc[v4*4+3]);
}

// ---------------- K3: offset head ----------------
__global__ void __launch_bounds__(64) k_off(
    const float* __restrict__ w1c, const float* __restrict__ b1c,
    const float* __restrict__ w2c) {
    __shared__ float qs3[64][65];
    __shared__ float contrib[64][8];
    __shared__ float tmp8[8];
    int ng = blockIdx.x, t = threadIdx.x;
    for (int p = 0; p < 64; p++) qs3[p][t] = g_q[ng * 4096 + p * 64 + t];
    float wr[36];
    #pragma unroll
    for (int u = 0; u < 36; u++) wr[u] = w1c[t * 36 + u];
    float bias = b1c[t], w2a = w2c[t], w2b = w2c[64 + t];
    __syncthreads();
    #pragma unroll
    for (int sy = 0; sy < 2; sy++)
    #pragma unroll
    for (int sx = 0; sx < 2; sx++) {
        float s = bias;
        #pragma unroll
        for (int ky = 0; ky < 6; ky++) {
            int iy = sy * 4 - 1 + ky;
            if (iy < 0 || iy > 7) continue;
            #pragma unroll
            for (int kx = 0; kx < 6; kx++) {
                int ix = sx * 4 - 1 + kx;
                if (ix < 0 || ix > 7) continue;
                s += wr[ky * 6 + kx] * qs3[t][iy * 8 + ix];
            }
        }
        float gl = 0.5f * s * (1.f + erff(s * 0.70710678118654752f));
        contrib[t][(sy * 2 + sx) * 2 + 0] = gl * w2a;
        contrib[t][(sy * 2 + sx) * 2 + 1] = gl * w2b;
    }
    __syncthreads();
    if (t < 8) {
        float s = 0.f;
        for (int cc = 0; cc < 64; cc++) s += contrib[cc][t];
        tmp8[t] = 4.f * tanhf(s);
    }
    __syncthreads();
    if (t < 4) {
        int sy = t >> 1, sx = t & 1;
        g_vs[ng * 8 + t * 2 + 0] = 2.f * ((float)sx + tmp8[t * 2 + 0]) - 1.f;
        g_vs[ng * 8 + t * 2 + 1] = 2.f * ((float)sy + tmp8[t * 2 + 1]) - 1.f;
    }
}

// ---------------- K4: bilinear KV gather + K/V proj (smem-staged) ----------------
// dyn smem: xp [128][65] (8320) | wks [2][64][129] (16512) | kvs [128][4] (512)
__global__ void __launch_bounds__(256) k_kv(
    const float* __restrict__ x, const float* __restrict__ lg,
    const float* __restrict__ lb, const float* __restrict__ wk,
    const float* __restrict__ wv) {
    extern __shared__ float sm[];
    float* xp  = sm;
    float* wks = sm + 8320;
    float* kvs = sm + 24832;
    int ng = blockIdx.x, n = ng >> 3, g = ng & 7;
    int b = n & 63, quad = n >> 6, qh = quad >> 1, qw = quad & 1;
    int t = threadIdx.x;
    #pragma unroll 8
    for (int p = 0; p < 32; p++) {
        int idx = t + (p << 8);
        int pos = idx & 63, i = idx >> 6;
        int y = (qh << 3) + (pos >> 3), xx = (qw << 3) + (pos & 7);
        int cc = (g << 7) + i;
        float raw = x[(b * 1024 + cc) * 256 + y * 16 + xx];
        int mid = (b << 8) + y * 16 + xx;
        xp[i * 65 + pos] = (raw - g_mu[mid]) * g_rstd[mid] * __ldg(lg + cc) + __ldg(lb + cc);
    }
    #pragma unroll 8
    for (int p = 0; p < 64; p++) {
        int idx = t + (p << 8);
        int which = idx >> 13, o = (idx >> 7) & 63, i = idx & 127;
        const float* wsrc = which ? wv : wk;
        wks[which * 8256 + o * 129 + i] = __ldg(wsrc + (g << 13) + (o << 7) + i);
    }
    __syncthreads();
    if (t < 128) {
        #pragma unroll
        for (int j = 0; j < 4; j++) {
            float vx = g_vs[ng * 8 + j * 2], vy = g_vs[ng * 8 + j * 2 + 1];
            float fx = ((vx + 1.f) * 8.f - 1.f) * 0.5f;
            float fy = ((vy + 1.f) * 8.f - 1.f) * 0.5f;
            float x0 = floorf(fx), y0 = floorf(fy);
            float wx1 = fx - x0, wy1 = fy - y0;
            float acc = 0.f;
            #pragma unroll
            for (int dy = 0; dy < 2; dy++)
            #pragma unroll
            for (int dx = 0; dx < 2; dx++) {
                float X = x0 + dx, Y = y0 + dy;
                if (X >= 0.f && X <= 7.f && Y >= 0.f && Y <= 7.f) {
                    float wgt = (dx ? wx1 : 1.f - wx1) * (dy ? wy1 : 1.f - wy1);
                    acc += wgt * xp[t * 65 + (int)Y * 8 + (int)X];
                }
            }
            kvs[t * 4 + j] = acc;
        }
    }
    __syncthreads();
    int o = t & 63, jp = (t >> 6) & 1, which = t >> 7;
    const float* wrow = wks + which * 8256 + o * 129;
    float a0 = 0.f, a1 = 0.f;
    #pragma unroll 4
    for (int i = 0; i < 128; i++) {
        float wt = wrow[i];
        a0 += wt * kvs[i * 4 + jp];
        a1 += wt * kvs[i * 4 + jp + 2];
    }
    float* dst = (which ? g_v : g_k) + (ng << 8);
    dst[jp * 64 + o] = a0;
    dst[(jp + 2) * 64 + o] = a1;
}

// ---------------- K5: CPB MLP (tf32 mma, 2x128-point passes) ----------------
// dyn smem floats: H1 [256][136] @0 (34816) | Ws [8][264] @34816 (2112) |
//                  w1s [3][256] @36928 (768) | bx @37696 | by @37952 | part[8][128] @38208
__global__ void __launch_bounds__(256) k_cpb(
    const float* __restrict__ w1, const float* __restrict__ b1,
    const float* __restrict__ w2, const float* __restrict__ b2,
    const float* __restrict__ w3, const float* __restrict__ b3) {
    extern __shared__ float sm[];
    float* H1  = sm;
    float* Ws  = sm + 34816;
    float* w1s = sm + 36928;
    float* bx  = sm + 37696;
    float* by  = sm + 37952;
    float* part = sm + 38208;
    int ng = blockIdx.x, t = threadIdx.x;
    int lane = t & 31, w = t >> 5, gid = lane >> 2, tig = lane & 3;
    w1s[t] = w1[t]; w1s[256 + t] = w1[256 + t]; w1s[512 + t] = b1[t];
    {
        int qi = t >> 2, j = t & 3;
        float gqx = (2.f / 7.f) * (float)(qi & 7) - 1.f;
        float gqy = (2.f / 7.f) * (float)(qi >> 3) - 1.f;
        float px = gqx - g_vs[ng * 8 + j * 2], py = gqy - g_vs[ng * 8 + j * 2 + 1];
        bx[t] = copysignf(log1pf(fabsf(px)), px);
        by[t] = copysignf(log1pf(fabsf(py)), py);
    }
    int m0 = w * 32;
    float b2a[2], b2b[2], w3r[4];
    b2a[0] = __ldg(b2 + m0 + gid);      b2b[0] = __ldg(b2 + m0 + gid + 8);
    b2a[1] = __ldg(b2 + m0 + 16 + gid); b2b[1] = __ldg(b2 + m0 + 24 + gid);
    w3r[0] = __ldg(w3 + m0 + gid);      w3r[1] = __ldg(w3 + m0 + gid + 8);
    w3r[2] = __ldg(w3 + m0 + 16 + gid); w3r[3] = __ldg(w3 + m0 + 24 + gid);
    float b3v = __ldg(b3);
    for (int np = 0; np < 2; np++) {
        __syncthreads();                       // H1/part from previous pass fully consumed
        {   // fill H1 [256 hidden][128 points], conflict-free column writes
            int col = t & 127, half = t >> 7;
            float bxv = bx[np * 128 + col], byv = by[np * 128 + col];
            #pragma unroll 4
            for (int r2 = 0; r2 < 128; r2++) {
                int r = half * 128 + r2;
                float h = fmaxf(w1s[r] * bxv + w1s[256 + r] * byv + w1s[512 + r], 0.f);
                H1[r * 136 + col] = __uint_as_float(f2tf(h));
            }
        }
        float c[2][16][4];
        #pragma unroll
        for (int mt = 0; mt < 2; mt++)
            #pragma unroll
            for (int nt = 0; nt < 16; nt++) {
                c[mt][nt][0] = b2a[mt]; c[mt][nt][1] = b2a[mt];
                c[mt][nt][2] = b2b[mt]; c[mt][nt][3] = b2b[mt];
            }
        for (int kc = 0; kc < 32; kc++) {
            int k0 = kc << 3;
            __syncthreads();                   // prior frag reads done (kc=0: H1 fill done)
            #pragma unroll
            for (int p = 0; p < 2; p++) {      // stage w2 rows k0..k0+7, coalesced
                int idx = t + (p << 8);
                int r = idx >> 6, mq = (idx & 63) << 2;
                float4 v4 = *(const float4*)(w2 + (k0 + r) * 256 + mq);
                float4 o4;
                o4.x = __uint_as_float(f2tf(v4.x)); o4.y = __uint_as_float(f2tf(v4.y));
                o4.z = __uint_as_float(f2tf(v4.z)); o4.w = __uint_as_float(f2tf(v4.w));
                *(float4*)(Ws + r * 264 + mq) = o4;
            }
            __syncthreads();
            unsigned a[2][4];
            #pragma unroll
            for (int mt = 0; mt < 2; mt++) {
                int m = m0 + mt * 16 + gid;
                a[mt][0] = __float_as_uint(Ws[tig * 264 + m]);
                a[mt][1] = __float_as_uint(Ws[tig * 264 + m + 8]);
                a[mt][2] = __float_as_uint(Ws[(tig + 4) * 264 + m]);
                a[mt][3] = __float_as_uint(Ws[(tig + 4) * 264 + m + 8]);
            }
            #pragma unroll
            for (int nt = 0; nt < 16; nt++) {
                unsigned b0 = __float_as_uint(H1[(k0 + tig) * 136 + nt * 8 + gid]);
                unsigned bv = __float_as_uint(H1[(k0 + tig + 4) * 136 + nt * 8 + gid]);
                mma8(c[0][nt], a[0], b0, bv);
                mma8(c[1][nt], a[1], b0, bv);
            }
        }
        float colsum[32];
        #pragma unroll
        for (int nt = 0; nt < 16; nt++)
            #pragma unroll
            for (int q = 0; q < 2; q++)
                colsum[nt * 2 + q] =
                    w3r[0] * fmaxf(c[0][nt][q], 0.f) + w3r[1] * fmaxf(c[0][nt][2 + q], 0.f) +
                    w3r[2] * fmaxf(c[1][nt][q], 0.f) + w3r[3] * fmaxf(c[1][nt][2 + q], 0.f);
        #pragma unroll
        for (int off = 4; off < 32; off <<= 1)
            #pragma unroll
            for (int i2 = 0; i2 < 32; i2++)
                colsum[i2] += __shfl_xor_sync(0xffffffffu, colsum[i2], off);
        if (gid == 0) {
            #pragma unroll
            for (int i2 = 0; i2 < 32; i2++)
                part[w * 128 + (i2 >> 1) * 8 + tig * 2 + (i2 & 1)] = colsum[i2];
        }
        __syncthreads();
        if (t < 128) {
            float s = 0.f;
            #pragma unroll
            for (int wi = 0; wi < 8; wi++) s += part[wi * 128 + t];
            g_bias[ng * 256 + np * 128 + t] = s + b3v;
        }
    }
}

// ---------------- K6: attention ----------------
__global__ void __launch_bounds__(256) k_att() {
    __shared__ float qs[64][65];
    __shared__ float ks4[4][65], vs4[4][65];
    __shared__ float att_s[64][5];
    int ng = blockIdx.x, n = ng >> 3, g = ng & 7;
    int t = threadIdx.x;
    #pragma unroll
    for (int p = 0; p < 16; p++) {
        int idx = t + (p << 8);
        qs[idx >> 6][idx & 63] = g_q[ng * 4096 + idx];
    }
    { int j = t >> 6, o = t & 63; ks4[j][o] = g_k[(ng << 8) + t]; vs4[j][o] = g_v[(ng << 8) + t]; }
    __syncthreads();
    int qi = t >> 2, j = t & 3;
    float s = 0.f;
    #pragma unroll 8
    for (int d = 0; d < 64; d++) s += qs[d][qi] * ks4[j][d];
    s = s * 0.125f + g_bias[(ng << 8) + t];
    float mx = fmaxf(s, __shfl_xor_sync(0xffffffffu, s, 1));
    mx = fmaxf(mx, __shfl_xor_sync(0xffffffffu, mx, 2));
    float e = __expf(s - mx);
    float sum = e;
    sum += __shfl_xor_sync(0xffffffffu, sum, 1);
    sum += __shfl_xor_sync(0xffffffffu, sum, 2);
    att_s[qi][j] = e / sum;
    __syncthreads();
    int qi2 = t & 63, dg = t >> 6;
    float a0 = att_s[qi2][0], a1 = att_s[qi2][1], a2 = att_s[qi2][2], a3 = att_s[qi2][3];
    #pragma unroll
    for (int dd = 0; dd < 16; dd++) {
        int d = (dg << 4) + dd;
        float r = a0 * vs4[0][d] + a1 * vs4[1][d] + a2 * vs4[2][d] + a3 * vs4[3][d];
        g_att[((g << 6) + d) * 16384 + (n << 6) + qi2] = r;
    }
}

// ---------------- K7: output projection, 3x tf32 split ----------------
__global__ void __launch_bounds__(256) k_out(
    const float* __restrict__ ow, const float* __restrict__ ob,
    float* __restrict__ out) {
    __shared__ float Ah[128 * 20], Al[128 * 20];
    __shared__ float Bh[16 * 136], Bl[16 * 136];
    int blk = blockIdx.x;
    int mb = (blk & 7) << 7, nb = (blk >> 3) << 7;
    int t = threadIdx.x, lane = t & 31, w = t >> 5;
    int gid = lane >> 2, tig = lane & 3;
    int mw = (w >> 2) << 6, nw = (w & 3) << 5;
    float c[4][4][4];
    #pragma unroll
    for (int mt = 0; mt < 4; mt++)
        #pragma unroll
        for (int nt = 0; nt < 4; nt++)
            #pragma unroll
            for (int q = 0; q < 4; q++) c[mt][nt][q] = 0.f;
    for (int ck = 0; ck < 32; ck++) {
        int k0 = ck << 4;
        #pragma unroll
        for (int sA = 0; sA < 2; sA++) {
            int r = (t >> 2) + sA * 64, kq = (t & 3) << 2;
            float4 av = *(const float4*)(ow + (mb + r) * 512 + k0 + kq);
            float vv[4] = {av.x, av.y, av.z, av.w};
            #pragma unroll
            for (int u = 0; u < 4; u++) {
                float h = __uint_as_float(f2tf(vv[u]));
                Ah[r * 20 + kq + u] = h;
                Al[r * 20 + kq + u] = __uint_as_float(f2tf(vv[u] - h));
            }
        }
        {
            int r = t >> 4, cq = (t & 15) << 3;
            const float4* gb = (const float4*)(g_att + (k0 + r) * 16384 + nb + cq);
            float4 b0 = gb[0], b1v = gb[1];
            float vv[8] = {b0.x, b0.y, b0.z, b0.w, b1v.x, b1v.y, b1v.z, b1v.w};
            #pragma unroll
            for (int u = 0; u < 8; u++) {
                float h = __uint_as_float(f2tf(vv[u]));
                Bh[r * 136 + cq + u] = h;
                Bl[r * 136 + cq + u] = __uint_as_float(f2tf(vv[u] - h));
            }
        }
        __syncthreads();
        #pragma unroll
        for (int ks = 0; ks < 2; ks++) {
            int kk = ks * 8 + tig;
            unsigned ah[4][4], al[4][4];
            #pragma unroll
            for (int mt = 0; mt < 4; mt++) {
                int m = mw + mt * 16 + gid;
                ah[mt][0] = __float_as_uint(Ah[m * 20 + kk]);
                ah[mt][1] = __float_as_uint(Ah[(m + 8) * 20 + kk]);
                ah[mt][2] = __float_as_uint(Ah[m * 20 + kk + 4]);
                ah[mt][3] = __float_as_uint(Ah[(m + 8) * 20 + kk + 4]);
                al[mt][0] = __float_as_uint(Al[m * 20 + kk]);
                al[mt][1] = __float_as_uint(Al[(m + 8) * 20 + kk]);
                al[mt][2] = __float_as_uint(Al[m * 20 + kk + 4]);
                al[mt][3] = __float_as_uint(Al[(m + 8) * 20 + kk + 4]);
            }
            #pragma unroll
            for (int nt = 0; nt < 4; nt++) {
                int col = nw + nt * 8 + gid;
                unsigned bh0 = __float_as_uint(Bh[kk * 136 + col]);
                unsigned bh1 = __float_as_uint(Bh[(kk + 4) * 136 + col]);
                unsigned bl0 = __float_as_uint(Bl[kk * 136 + col]);
                unsigned bl1 = __float_as_uint(Bl[(kk + 4) * 136 + col]);
                #pragma unroll
                for (int mt = 0; mt < 4; mt++) {
                    mma8(c[mt][nt], ah[mt], bh0, bh1);
                    mma8(c[mt][nt], al[mt], bh0, bh1);
                    mma8(c[mt][nt], ah[mt], bl0, bl1);
                }
            }
        }
        __syncthreads();
    }
    #pragma unroll
    for (int mt = 0; mt < 4; mt++)
        #pragma unroll
        for (int nt = 0; nt < 4; nt++)
            #pragma unroll
            for (int q = 0; q < 4; q++) {
                int o = mb + mw + mt * 16 + gid + ((q >> 1) << 3);
                int col = nb + nw + nt * 8 + tig * 2 + (q & 1);
                int n = col >> 6, qi = col & 63;
                int b = n & 63, quad = n >> 6;
                int y = ((quad >> 1) << 3) + (qi >> 3);
                int xx = ((quad & 1) << 3) + (qi & 7);
                out[((b * 1024 + o) * 16 + y) * 16 + xx] = c[mt][nt][q] + __ldg(ob + o);
            }
}

extern "C" void kernel_launch(void* const* d_in, const int* in_sizes, int n_in,
                              void* d_out, int out_size) {
    const float* x      = (const float*)d_in[0];
    const float* ln_g   = (const float*)d_in[1];
    const float* ln_b   = (const float*)d_in[2];
    const float* wq     = (const float*)d_in[3];
    const float* wk     = (const float*)d_in[4];
    const float* wv     = (const float*)d_in[5];
    const float* off_w1 = (const float*)d_in[6];
    const float* off_b1 = (const float*)d_in[7];
    const float* off_w2 = (const float*)d_in[8];
    const float* cpb_w1 = (const float*)d_in[9];
    const float* cpb_b1 = (const float*)d_in[10];
    const float* cpb_w2 = (const float*)d_in[11];
    const float* cpb_b2 = (const float*)d_in[12];
    const float* cpb_w3 = (const float*)d_in[13];
    const float* cpb_b3 = (const float*)d_in[14];
    const float* out_w  = (const float*)d_in[15];
    const float* out_b  = (const float*)d_in[16];
    float* out = (float*)d_out;
    const int KV_SMEM  = 25344 * 4;   // 101376 B
    const int CPB_SMEM = 39232 * 4;   // 156928 B
    cudaFuncSetAttribute(k_kv,  cudaFuncAttributeMaxDynamicSharedMemorySize, KV_SMEM);
    cudaFuncSetAttribute(k_cpb, cudaFuncAttributeMaxDynamicSharedMemorySize, CPB_SMEM);
    k_ln<<<512, 256>>>(x);
    k_qproj<<<2048, 256>>>(x, ln_g, ln_b, wq);
    k_off<<<2048, 64>>>(off_w1, off_b1, off_w2);
    k_kv<<<2048, 256, KV_SMEM>>>(x, ln_g, ln_b, wk, wv);
    k_cpb<<<2048, 256, CPB_SMEM>>>(cpb_w1, cpb_b1, cpb_w2, cpb_b2, cpb_w3, cpb_b3);
    k_att<<<2048, 256>>>();
    k_out<<<1024, 256>>>(out_w, out_b, out);
}

// round 5
// speedup vs baseline: 2.0259x; 1.9191x over previous
#include <cuda_runtime.h>
#include <cuda_bf16.h>
#include <math.h>

#define DEVI __device__ __forceinline__

__device__ float g_mu[16384];
__device__ float g_rstd[16384];
__device__ float g_q[2048 * 4096];     // [ng][o][pos]
__device__ float g_vs[2048 * 8];       // [ng][j][x,y]
__device__ float g_k[2048 * 256];      // [ng][j][o]
__device__ float g_v[2048 * 256];
__device__ float g_bias[2048 * 256];   // [ng][qi*4+j]
__device__ float g_att[512 * 16384];   // [c][n*64+qi]

DEVI void mma16(float* c, const unsigned* a, unsigned b0, unsigned b1) {
    asm("mma.sync.aligned.m16n8k16.row.col.f32.bf16.bf16.f32 "
        "{%0,%1,%2,%3}, {%4,%5,%6,%7}, {%8,%9}, {%0,%1,%2,%3};"
        : "+f"(c[0]), "+f"(c[1]), "+f"(c[2]), "+f"(c[3])
        : "r"(a[0]), "r"(a[1]), "r"(a[2]), "r"(a[3]), "r"(b0), "r"(b1));
}
DEVI unsigned pack_bf2(float lo, float hi) {
    unsigned a = (unsigned)__bfloat16_as_ushort(__float2bfloat16_rn(lo));
    unsigned b = (unsigned)__bfloat16_as_ushort(__float2bfloat16_rn(hi));
    return a | (b << 16);
}
DEVI void split_bf(float v, unsigned short& h, unsigned short& m) {
    __nv_bfloat16 bh = __float2bfloat16_rn(v);
    float hv = __bfloat162float(bh);
    h = __bfloat16_as_ushort(bh);
    m = __bfloat16_as_ushort(__float2bfloat16_rn(v - hv));
}

// ---------------- K1: LayerNorm stats ----------------
__global__ void __launch_bounds__(256) k_ln(const float* __restrict__ x) {
    int b = blockIdx.x >> 3, rp = blockIdx.x & 7;
    int t = threadIdx.x, pl = t & 31, w = t >> 5;
    const float* px = x + b * 262144 + rp * 32 + pl;
    float s = 0.f, q = 0.f;
    for (int c = w; c < 1024; c += 8) { float v = px[c * 256]; s += v; q += v * v; }
    __shared__ float rs[8][32], rq[8][32];
    rs[w][pl] = s; rq[w][pl] = q;
    __syncthreads();
    if (t < 32) {
        float S = 0.f, Q = 0.f;
        #pragma unroll
        for (int i = 0; i < 8; i++) { S += rs[i][t]; Q += rq[i][t]; }
        float mu = S * (1.f / 1024.f);
        float var = Q * (1.f / 1024.f) - mu * mu;
        g_mu[b * 256 + rp * 32 + t] = mu;
        g_rstd[b * 256 + rp * 32 + t] = rsqrtf(var + 1e-6f);
    }
}

// ---------------- K2: Q projection (smem-staged weights) ----------------
// dyn smem: xns [128][64] @0 (8192) | wqs [64][129] @8192 (8256) -> 65792 B
__global__ void __launch_bounds__(256) k_qproj(
    const float* __restrict__ x, const float* __restrict__ lg,
    const float* __restrict__ lb, const float* __restrict__ wq) {
    extern __shared__ float smq[];
    float* xns = smq;
    float* wqs = smq + 8192;
    int ng = blockIdx.x, n = ng >> 3, g = ng & 7;
    int b = n & 63, quad = n >> 6, qh = quad >> 1, qw = quad & 1;
    int t = threadIdx.x;
    #pragma unroll 8
    for (int pass = 0; pass < 32; pass++) {
        int e = t + (pass << 8);
        int pos = e & 63, i = e >> 6;
        int y = (qh << 3) + (pos >> 3), xx = (qw << 3) + (pos & 7);
        int cc = (g << 7) + i;
        float raw = x[(b * 1024 + cc) * 256 + y * 16 + xx];
        int mid = (b << 8) + y * 16 + xx;
        xns[i * 64 + pos] = (raw - g_mu[mid]) * g_rstd[mid] * __ldg(lg + cc) + __ldg(lb + cc);
        int o = e >> 7, i2 = e & 127;
        wqs[o * 129 + i2] = __ldg(wq + (g << 13) + e);
    }
    __syncthreads();
    int o = t & 63, pb = t >> 6;
    float acc[16];
    #pragma unroll
    for (int u = 0; u < 16; u++) acc[u] = 0.f;
    #pragma unroll 2
    for (int i = 0; i < 128; i++) {
        float wv = wqs[o * 129 + i];
        const float4* xr = (const float4*)&xns[i * 64 + (pb << 4)];
        #pragma unroll
        for (int v4 = 0; v4 < 4; v4++) {
            float4 xv = xr[v4];
            acc[v4*4+0] += wv*xv.x; acc[v4*4+1] += wv*xv.y;
            acc[v4*4+2] += wv*xv.z; acc[v4*4+3] += wv*xv.w;
        }
    }
    float* op = g_q + ng * 4096 + (o << 6) + (pb << 4);
    #pragma unroll
    for (int v4 = 0; v4 < 4; v4++)
        ((float4*)op)[v4] = make_float4(acc[v4*4], acc[v4*4+1], acc[v4*4+2], acc[v4*4+3]);
}

// ---------------- K3: offset head ----------------
__global__ void __launch_bounds__(64) k_off(
    const float* __restrict__ w1c, const float* __restrict__ b1c,
    const float* __restrict__ w2c) {
    __shared__ float qs3[64][65];
    __shared__ float contrib[64][8];
    __shared__ float tmp8[8];
    int ng = blockIdx.x, t = threadIdx.x;
    for (int p = 0; p < 64; p++) qs3[p][t] = g_q[ng * 4096 + p * 64 + t];
    float wr[36];
    #pragma unroll
    for (int u = 0; u < 36; u++) wr[u] = w1c[t * 36 + u];
    float bias = b1c[t], w2a = w2c[t], w2b = w2c[64 + t];
    __syncthreads();
    #pragma unroll
    for (int sy = 0; sy < 2; sy++)
    #pragma unroll
    for (int sx = 0; sx < 2; sx++) {
        float s = bias;
        #pragma unroll
        for (int ky = 0; ky < 6; ky++) {
            int iy = sy * 4 - 1 + ky;
            if (iy < 0 || iy > 7) continue;
            #pragma unroll
            for (int kx = 0; kx < 6; kx++) {
                int ix = sx * 4 - 1 + kx;
                if (ix < 0 || ix > 7) continue;
                s += wr[ky * 6 + kx] * qs3[t][iy * 8 + ix];
            }
        }
        float gl = 0.5f * s * (1.f + erff(s * 0.70710678118654752f));
        contrib[t][(sy * 2 + sx) * 2 + 0] = gl * w2a;
        contrib[t][(sy * 2 + sx) * 2 + 1] = gl * w2b;
    }
    __syncthreads();
    if (t < 8) {
        float s = 0.f;
        for (int cc = 0; cc < 64; cc++) s += contrib[cc][t];
        tmp8[t] = 4.f * tanhf(s);
    }
    __syncthreads();
    if (t < 4) {
        int sy = t >> 1, sx = t & 1;
        g_vs[ng * 8 + t * 2 + 0] = 2.f * ((float)sx + tmp8[t * 2 + 0]) - 1.f;
        g_vs[ng * 8 + t * 2 + 1] = 2.f * ((float)sy + tmp8[t * 2 + 1]) - 1.f;
    }
}

// ---------------- K4: bilinear KV gather + K/V proj (8 ngs per block) ----------------
// grid 256: g = bid&7, 8 ngs of same g. dyn smem: wks 16512 | xp 8320 | kvs 512
__global__ void __launch_bounds__(256) k_kv(
    const float* __restrict__ x, const float* __restrict__ lg,
    const float* __restrict__ lb, const float* __restrict__ wk,
    const float* __restrict__ wv) {
    extern __shared__ float sm[];
    float* wks = sm;
    float* xp  = sm + 16512;
    float* kvs = sm + 24832;
    int bid = blockIdx.x, g = bid & 7, nt0 = (bid >> 3) << 3;
    int t = threadIdx.x;
    #pragma unroll 8
    for (int p = 0; p < 64; p++) {
        int idx = t + (p << 8);
        int which = idx >> 13, o = (idx >> 7) & 63, i = idx & 127;
        const float* wsrc = which ? wv : wk;
        wks[which * 8256 + o * 129 + i] = __ldg(wsrc + (g << 13) + (o << 7) + i);
    }
    for (int n8 = 0; n8 < 8; n8++) {
        int n = nt0 + n8, ng = n * 8 + g;
        int b = n & 63, quad = n >> 6, qh = quad >> 1, qw = quad & 1;
        #pragma unroll 8
        for (int p = 0; p < 32; p++) {
            int idx = t + (p << 8);
            int pos = idx & 63, i = idx >> 6;
            int y = (qh << 3) + (pos >> 3), xx = (qw << 3) + (pos & 7);
            int cc = (g << 7) + i;
            float raw = x[(b * 1024 + cc) * 256 + y * 16 + xx];
            int mid = (b << 8) + y * 16 + xx;
            xp[i * 65 + pos] = (raw - g_mu[mid]) * g_rstd[mid] * __ldg(lg + cc) + __ldg(lb + cc);
        }
        __syncthreads();
        if (t < 128) {
            #pragma unroll
            for (int j = 0; j < 4; j++) {
                float vx = g_vs[ng * 8 + j * 2], vy = g_vs[ng * 8 + j * 2 + 1];
                float fx = ((vx + 1.f) * 8.f - 1.f) * 0.5f;
                float fy = ((vy + 1.f) * 8.f - 1.f) * 0.5f;
                float x0 = floorf(fx), y0 = floorf(fy);
                float wx1 = fx - x0, wy1 = fy - y0;
                float acc = 0.f;
                #pragma unroll
                for (int dy = 0; dy < 2; dy++)
                #pragma unroll
                for (int dx = 0; dx < 2; dx++) {
                    float X = x0 + dx, Y = y0 + dy;
                    if (X >= 0.f && X <= 7.f && Y >= 0.f && Y <= 7.f) {
                        float wgt = (dx ? wx1 : 1.f - wx1) * (dy ? wy1 : 1.f - wy1);
                        acc += wgt * xp[t * 65 + (int)Y * 8 + (int)X];
                    }
                }
                kvs[t * 4 + j] = acc;
            }
        }
        __syncthreads();
        int o = t & 63, jp = (t >> 6) & 1, which = t >> 7;
        const float* wrow = wks + which * 8256 + o * 129;
        float a0 = 0.f, a1 = 0.f;
        #pragma unroll 4
        for (int i = 0; i < 128; i++) {
            float wt = wrow[i];
            a0 += wt * kvs[i * 4 + jp];
            a1 += wt * kvs[i * 4 + jp + 2];
        }
        float* dst = (which ? g_v : g_k) + (ng << 8);
        dst[jp * 64 + o] = a0;
        dst[(jp + 2) * 64 + o] = a1;
    }
}

// ---------------- K5: CPB MLP, bf16 m16n8k16 ----------------
// 512 threads (16 warps, 16 m-rows each). dyn smem floats:
// H1p(u32) 128*136 @0 (17408) | Wsp(u32) 8*264 @17408 (2112) | w1s @19520 (768)
// bx @20288 | by @20544 | part 16*128 @20800 -> 22848 floats = 91392 B
__global__ void __launch_bounds__(512) k_cpb(
    const float* __restrict__ w1, const float* __restrict__ b1,
    const float* __restrict__ w2, const float* __restrict__ b2,
    const float* __restrict__ w3, const float* __restrict__ b3) {
    extern __shared__ float sm[];
    unsigned* H1p = (unsigned*)sm;
    unsigned* Wsp = (unsigned*)(sm + 17408);
    float* w1s = sm + 19520;
    float* bx  = sm + 20288;
    float* by  = sm + 20544;
    float* part = sm + 20800;
    int ng = blockIdx.x, t = threadIdx.x;
    int lane = t & 31, w = t >> 5, gid = lane >> 2, tig = lane & 3;
    if (t < 256) {
        w1s[t] = w1[t]; w1s[256 + t] = w1[256 + t]; w1s[512 + t] = b1[t];
        int qi = t >> 2, j = t & 3;
        float gqx = (2.f / 7.f) * (float)(qi & 7) - 1.f;
        float gqy = (2.f / 7.f) * (float)(qi >> 3) - 1.f;
        float px = gqx - g_vs[ng * 8 + j * 2], py = gqy - g_vs[ng * 8 + j * 2 + 1];
        bx[t] = copysignf(log1pf(fabsf(px)), px);
        by[t] = copysignf(log1pf(fabsf(py)), py);
    }
    int m0 = w << 4;
    float b2a = __ldg(b2 + m0 + gid), b2b = __ldg(b2 + m0 + gid + 8);
    float w3a = __ldg(w3 + m0 + gid), w3b = __ldg(w3 + m0 + gid + 8);
    float b3v = __ldg(b3);
    int sr = t >> 6, mq = (t & 63) << 2;        // staging coords
    __syncthreads();
    for (int np = 0; np < 2; np++) {
        {   // fill H1 (bf16 pairs), cols = points
            int col = t & 127, pr0 = (t >> 7) << 5;
            float bxv = bx[np * 128 + col], byv = by[np * 128 + col];
            #pragma unroll 4
            for (int r = 0; r < 32; r++) {
                int pr = pr0 + r;
                float h0 = fmaxf(w1s[2 * pr] * bxv + w1s[256 + 2 * pr] * byv + w1s[512 + 2 * pr], 0.f);
                float h1 = fmaxf(w1s[2 * pr + 1] * bxv + w1s[256 + 2 * pr + 1] * byv + w1s[512 + 2 * pr + 1], 0.f);
                H1p[pr * 136 + col] = pack_bf2(h0, h1);
            }
        }
        float c[16][4];
        #pragma unroll
        for (int nt = 0; nt < 16; nt++) { c[nt][0] = b2a; c[nt][1] = b2a; c[nt][2] = b2b; c[nt][3] = b2b; }
        float4 pa = *(const float4*)(w2 + (2 * sr) * 256 + mq);
        float4 pb = *(const float4*)(w2 + (2 * sr + 1) * 256 + mq);
        for (int kc = 0; kc < 16; kc++) {
            __syncthreads();     // H1 ready / Wsp consumed
            Wsp[sr * 264 + mq + 0] = pack_bf2(pa.x, pb.x);
            Wsp[sr * 264 + mq + 1] = pack_bf2(pa.y, pb.y);
            Wsp[sr * 264 + mq + 2] = pack_bf2(pa.z, pb.z);
            Wsp[sr * 264 + mq + 3] = pack_bf2(pa.w, pb.w);
            __syncthreads();
            if (kc < 15) {
                pa = *(const float4*)(w2 + (16 * (kc + 1) + 2 * sr) * 256 + mq);
                pb = *(const float4*)(w2 + (16 * (kc + 1) + 2 * sr + 1) * 256 + mq);
            }
            unsigned a[4];
            a[0] = Wsp[tig * 264 + m0 + gid];
            a[1] = Wsp[tig * 264 + m0 + gid + 8];
            a[2] = Wsp[(tig + 4) * 264 + m0 + gid];
            a[3] = Wsp[(tig + 4) * 264 + m0 + gid + 8];
            #pragma unroll
            for (int nt = 0; nt < 16; nt++) {
                unsigned b0 = H1p[(kc * 8 + tig) * 136 + nt * 8 + gid];
                unsigned bv = H1p[(kc * 8 + tig + 4) * 136 + nt * 8 + gid];
                mma16(c[nt], a, b0, bv);
            }
        }
        float colsum[32];
        #pragma unroll
        for (int nt = 0; nt < 16; nt++)
            #pragma unroll
            for (int q = 0; q < 2; q++)
                colsum[nt * 2 + q] = w3a * fmaxf(c[nt][q], 0.f) + w3b * fmaxf(c[nt][2 + q], 0.f);
        #pragma unroll
        for (int off = 4; off < 32; off <<= 1)
            #pragma unroll
            for (int i2 = 0; i2 < 32; i2++)
                colsum[i2] += __shfl_xor_sync(0xffffffffu, colsum[i2], off);
        if (gid == 0) {
            #pragma unroll
            for (int i2 = 0; i2 < 32; i2++)
                part[w * 128 + (i2 >> 1) * 8 + tig * 2 + (i2 & 1)] = colsum[i2];
        }
        __syncthreads();
        if (t < 128) {
            float s = 0.f;
            #pragma unroll
            for (int wi = 0; wi < 16; wi++) s += part[wi * 128 + t];
            g_bias[ng * 256 + np * 128 + t] = s + b3v;
        }
        __syncthreads();   // part/H1 consumed before next np overwrites
    }
}

// ---------------- K6: attention ----------------
__global__ void __launch_bounds__(256) k_att() {
    __shared__ float qs[64][65];
    __shared__ float ks4[4][65], vs4[4][65];
    __shared__ float att_s[64][5];
    int ng = blockIdx.x, n = ng >> 3, g = ng & 7;
    int t = threadIdx.x;
    #pragma unroll
    for (int p = 0; p < 16; p++) {
        int idx = t + (p << 8);
        qs[idx >> 6][idx & 63] = g_q[ng * 4096 + idx];
    }
    { int j = t >> 6, o = t & 63; ks4[j][o] = g_k[(ng << 8) + t]; vs4[j][o] = g_v[(ng << 8) + t]; }
    __syncthreads();
    int qi = t >> 2, j = t & 3;
    float s = 0.f;
    #pragma unroll 8
    for (int d = 0; d < 64; d++) s += qs[d][qi] * ks4[j][d];
    s = s * 0.125f + g_bias[(ng << 8) + t];
    float mx = fmaxf(s, __shfl_xor_sync(0xffffffffu, s, 1));
    mx = fmaxf(mx, __shfl_xor_sync(0xffffffffu, mx, 2));
    float e = __expf(s - mx);
    float sum = e;
    sum += __shfl_xor_sync(0xffffffffu, sum, 1);
    sum += __shfl_xor_sync(0xffffffffu, sum, 2);
    att_s[qi][j] = e / sum;
    __syncthreads();
    int qi2 = t & 63, dg = t >> 6;
    float a0 = att_s[qi2][0], a1 = att_s[qi2][1], a2 = att_s[qi2][2], a3 = att_s[qi2][3];
    #pragma unroll
    for (int dd = 0; dd < 16; dd++) {
        int d = (dg << 4) + dd;
        float r = a0 * vs4[0][d] + a1 * vs4[1][d] + a2 * vs4[2][d] + a3 * vs4[3][d];
        g_att[((g << 6) + d) * 16384 + (n << 6) + qi2] = r;
    }
}

// ---------------- K7: output projection, bf16 2-term split (3 mmas k16) ----------------
__global__ void __launch_bounds__(256) k_out(
    const float* __restrict__ ow, const float* __restrict__ ob,
    float* __restrict__ out) {
    __shared__ unsigned Ah[8 * 136], Am[8 * 136], Bh2[8 * 136], Bm2[8 * 136];
    int blk = blockIdx.x;
    int mb = (blk & 7) << 7, nb = (blk >> 3) << 7;
    int t = threadIdx.x, lane = t & 31, w = t >> 5;
    int gid = lane >> 2, tig = lane & 3;
    int mw = (w >> 2) << 6, nw = (w & 3) << 5;
    float c[4][4][4];
    #pragma unroll
    for (int mt = 0; mt < 4; mt++)
        #pragma unroll
        for (int nt = 0; nt < 4; nt++)
            #pragma unroll
            for (int q = 0; q < 4; q++) c[mt][nt][q] = 0.f;
    int ar = t >> 1, akq = (t & 1) << 3;
    int brp = t >> 5, bcq = (t & 31) << 2;
    for (int ck = 0; ck < 32; ck++) {
        int k0 = ck << 4;
        float4 a0 = *(const float4*)(ow + (mb + ar) * 512 + k0 + akq);
        float4 a1 = *(const float4*)(ow + (mb + ar) * 512 + k0 + akq + 4);
        float4 bb0 = *(const float4*)(g_att + (k0 + 2 * brp) * 16384 + nb + bcq);
        float4 bb1 = *(const float4*)(g_att + (k0 + 2 * brp + 1) * 16384 + nb + bcq);
        __syncthreads();   // prev iter frag reads done
        {
            float av[8] = {a0.x, a0.y, a0.z, a0.w, a1.x, a1.y, a1.z, a1.w};
            #pragma unroll
            for (int jj = 0; jj < 4; jj++) {
                unsigned short h0, m0v, h1, m1v;
                split_bf(av[jj * 2], h0, m0v);
                split_bf(av[jj * 2 + 1], h1, m1v);
                int p = (akq >> 1) + jj;
                Ah[p * 136 + ar] = (unsigned)h0 | ((unsigned)h1 << 16);
                Am[p * 136 + ar] = (unsigned)m0v | ((unsigned)m1v << 16);
            }
            float bv0[4] = {bb0.x, bb0.y, bb0.z, bb0.w};
            float bv1[4] = {bb1.x, bb1.y, bb1.z, bb1.w};
            #pragma unroll
            for (int jj = 0; jj < 4; jj++) {
                unsigned short h0, m0v, h1, m1v;
                split_bf(bv0[jj], h0, m0v);
                split_bf(bv1[jj], h1, m1v);
                Bh2[brp * 136 + bcq + jj] = (unsigned)h0 | ((unsigned)h1 << 16);
                Bm2[brp * 136 + bcq + jj] = (unsigned)m0v | ((unsigned)m1v << 16);
            }
        }
        __syncthreads();
        unsigned ah[4][4], am[4][4];
        #pragma unroll
        for (int mt = 0; mt < 4; mt++) {
            int m = mw + mt * 16 + gid;
            ah[mt][0] = Ah[tig * 136 + m];       am[mt][0] = Am[tig * 136 + m];
            ah[mt][1] = Ah[tig * 136 + m + 8];   am[mt][1] = Am[tig * 136 + m + 8];
            ah[mt][2] = Ah[(tig + 4) * 136 + m]; am[mt][2] = Am[(tig + 4) * 136 + m];
            ah[mt][3] = Ah[(tig + 4) * 136 + m + 8]; am[mt][3] = Am[(tig + 4) * 136 + m + 8];
        }
        #pragma unroll
        for (int nt = 0; nt < 4; nt++) {
            int col = nw + nt * 8 + gid;
            unsigned bh0 = Bh2[tig * 136 + col], bh1 = Bh2[(tig + 4) * 136 + col];
            unsigned bm0 = Bm2[tig * 136 + col], bm1 = Bm2[(tig + 4) * 136 + col];
            #pragma unroll
            for (int mt = 0; mt < 4; mt++) {
                mma16(c[mt][nt], ah[mt], bh0, bh1);
                mma16(c[mt][nt], am[mt], bh0, bh1);
                mma16(c[mt][nt], ah[mt], bm0, bm1);
            }
        }
    }
    #pragma unroll
    for (int mt = 0; mt < 4; mt++)
        #pragma unroll
        for (int nt = 0; nt < 4; nt++)
            #pragma unroll
            for (int q = 0; q < 4; q++) {
                int o = mb + mw + mt * 16 + gid + ((q >> 1) << 3);
                int col = nb + nw + nt * 8 + tig * 2 + (q & 1);
                int n = col >> 6, qi = col & 63;
                int b = n & 63, quad = n >> 6;
                int y = ((quad >> 1) << 3) + (qi >> 3);
                int xx = ((quad & 1) << 3) + (qi & 7);
                out[((b * 1024 + o) * 16 + y) * 16 + xx] = c[mt][nt][q] + __ldg(ob + o);
            }
}

extern "C" void kernel_launch(void* const* d_in, const int* in_sizes, int n_in,
                              void* d_out, int out_size) {
    const float* x      = (const float*)d_in[0];
    const float* ln_g   = (const float*)d_in[1];
    const float* ln_b   = (const float*)d_in[2];
    const float* wq     = (const float*)d_in[3];
    const float* wk     = (const float*)d_in[4];
    const float* wv     = (const float*)d_in[5];
    const float* off_w1 = (const float*)d_in[6];
    const float* off_b1 = (const float*)d_in[7];
    const float* off_w2 = (const float*)d_in[8];
    const float* cpb_w1 = (const float*)d_in[9];
    const float* cpb_b1 = (const float*)d_in[10];
    const float* cpb_w2 = (const float*)d_in[11];
    const float* cpb_b2 = (const float*)d_in[12];
    const float* cpb_w3 = (const float*)d_in[13];
    const float* cpb_b3 = (const float*)d_in[14];
    const float* out_w  = (const float*)d_in[15];
    const float* out_b  = (const float*)d_in[16];
    float* out = (float*)d_out;
    const int QP_SMEM  = 16448 * 4;   // 65792 B
    const int KV_SMEM  = 25344 * 4;   // 101376 B
    const int CPB_SMEM = 22848 * 4;   // 91392 B
    cudaFuncSetAttribute(k_qproj, cudaFuncAttributeMaxDynamicSharedMemorySize, QP_SMEM);
    cudaFuncSetAttribute(k_kv,  cudaFuncAttributeMaxDynamicSharedMemorySize, KV_SMEM);
    cudaFuncSetAttribute(k_cpb, cudaFuncAttributeMaxDynamicSharedMemorySize, CPB_SMEM);
    k_ln<<<512, 256>>>(x);
    k_qproj<<<2048, 256, QP_SMEM>>>(x, ln_g, ln_b, wq);
    k_off<<<2048, 64>>>(off_w1, off_b1, off_w2);
    k_kv<<<256, 256, KV_SMEM>>>(x, ln_g, ln_b, wk, wv);
    k_cpb<<<2048, 512, CPB_SMEM>>>(cpb_w1, cpb_b1, cpb_w2, cpb_b2, cpb_w3, cpb_b3);
    k_att<<<2048, 256>>>();
    k_out<<<1024, 256>>>(out_w, out_b, out);
}

// round 6
// speedup vs baseline: 2.2845x; 1.1276x over previous
#include <cuda_runtime.h>
#include <cuda_bf16.h>
#include <math.h>

#define DEVI __device__ __forceinline__

__device__ float g_mu[16384];
__device__ float g_rstd[16384];
__device__ float g_q[2048 * 4096];     // [ng][o][pos]
__device__ float g_vs[2048 * 8];       // [ng][j][x,y]
__device__ float g_k[2048 * 256];      // [ng][j][o]
__device__ float g_v[2048 * 256];
__device__ float g_bias[2048 * 256];   // [ng][qi*4+j]
__device__ float g_att[512 * 16384];   // [c][n*64+qi]
__device__ unsigned g_w2bf[32768];     // [k2=128][m=256] packed bf16x2 of w2 rows 2k2,2k2+1

DEVI void mma16(float* c, const unsigned* a, unsigned b0, unsigned b1) {
    asm("mma.sync.aligned.m16n8k16.row.col.f32.bf16.bf16.f32 "
        "{%0,%1,%2,%3}, {%4,%5,%6,%7}, {%8,%9}, {%0,%1,%2,%3};"
        : "+f"(c[0]), "+f"(c[1]), "+f"(c[2]), "+f"(c[3])
        : "r"(a[0]), "r"(a[1]), "r"(a[2]), "r"(a[3]), "r"(b0), "r"(b1));
}
DEVI unsigned pack_bf2(float lo, float hi) {
    unsigned a = (unsigned)__bfloat16_as_ushort(__float2bfloat16_rn(lo));
    unsigned b = (unsigned)__bfloat16_as_ushort(__float2bfloat16_rn(hi));
    return a | (b << 16);
}
DEVI void split_bf(float v, unsigned short& h, unsigned short& m) {
    __nv_bfloat16 bh = __float2bfloat16_rn(v);
    float hv = __bfloat162float(bh);
    h = __bfloat16_as_ushort(bh);
    m = __bfloat16_as_ushort(__float2bfloat16_rn(v - hv));
}

// ---------------- K0: pack w2 to bf16x2 A-fragment layout ----------------
__global__ void __launch_bounds__(256) k_prep(const float* __restrict__ w2) {
    int idx = blockIdx.x * 256 + threadIdx.x;   // 32768 total
    int k2 = idx >> 8, m = idx & 255;
    g_w2bf[idx] = pack_bf2(w2[(2 * k2) * 256 + m], w2[(2 * k2 + 1) * 256 + m]);
}

// ---------------- K1: LayerNorm stats ----------------
__global__ void __launch_bounds__(256) k_ln(const float* __restrict__ x) {
    int b = blockIdx.x >> 3, rp = blockIdx.x & 7;
    int t = threadIdx.x, pl = t & 31, w = t >> 5;
    const float* px = x + b * 262144 + rp * 32 + pl;
    float s = 0.f, q = 0.f;
    for (int c = w; c < 1024; c += 8) { float v = px[c * 256]; s += v; q += v * v; }
    __shared__ float rs[8][32], rq[8][32];
    rs[w][pl] = s; rq[w][pl] = q;
    __syncthreads();
    if (t < 32) {
        float S = 0.f, Q = 0.f;
        #pragma unroll
        for (int i = 0; i < 8; i++) { S += rs[i][t]; Q += rq[i][t]; }
        float mu = S * (1.f / 1024.f);
        float var = Q * (1.f / 1024.f) - mu * mu;
        g_mu[b * 256 + rp * 32 + t] = mu;
        g_rstd[b * 256 + rp * 32 + t] = rsqrtf(var + 1e-6f);
    }
}

// ---------------- K2: Q projection (smem-staged weights) ----------------
__global__ void __launch_bounds__(256) k_qproj(
    const float* __restrict__ x, const float* __restrict__ lg,
    const float* __restrict__ lb, const float* __restrict__ wq) {
    extern __shared__ float smq[];
    float* xns = smq;
    float* wqs = smq + 8192;
    int ng = blockIdx.x, n = ng >> 3, g = ng & 7;
    int b = n & 63, quad = n >> 6, qh = quad >> 1, qw = quad & 1;
    int t = threadIdx.x;
    #pragma unroll 8
    for (int pass = 0; pass < 32; pass++) {
        int e = t + (pass << 8);
        int pos = e & 63, i = e >> 6;
        int y = (qh << 3) + (pos >> 3), xx = (qw << 3) + (pos & 7);
        int cc = (g << 7) + i;
        float raw = x[(b * 1024 + cc) * 256 + y * 16 + xx];
        int mid = (b << 8) + y * 16 + xx;
        xns[i * 64 + pos] = (raw - g_mu[mid]) * g_rstd[mid] * __ldg(lg + cc) + __ldg(lb + cc);
        int o = e >> 7, i2 = e & 127;
        wqs[o * 129 + i2] = __ldg(wq + (g << 13) + e);
    }
    __syncthreads();
    int o = t & 63, pb = t >> 6;
    float acc[16];
    #pragma unroll
    for (int u = 0; u < 16; u++) acc[u] = 0.f;
    #pragma unroll 2
    for (int i = 0; i < 128; i++) {
        float wv = wqs[o * 129 + i];
        const float4* xr = (const float4*)&xns[i * 64 + (pb << 4)];
        #pragma unroll
        for (int v4 = 0; v4 < 4; v4++) {
            float4 xv = xr[v4];
            acc[v4*4+0] += wv*xv.x; acc[v4*4+1] += wv*xv.y;
            acc[v4*4+2] += wv*xv.z; acc[v4*4+3] += wv*xv.w;
        }
    }
    float* op = g_q + ng * 4096 + (o << 6) + (pb << 4);
    #pragma unroll
    for (int v4 = 0; v4 < 4; v4++)
        ((float4*)op)[v4] = make_float4(acc[v4*4], acc[v4*4+1], acc[v4*4+2], acc[v4*4+3]);
}

// ---------------- K3: offset head ----------------
__global__ void __launch_bounds__(64) k_off(
    const float* __restrict__ w1c, const float* __restrict__ b1c,
    const float* __restrict__ w2c) {
    __shared__ float qs3[64][65];
    __shared__ float contrib[64][8];
    __shared__ float tmp8[8];
    int ng = blockIdx.x, t = threadIdx.x;
    for (int p = 0; p < 64; p++) qs3[p][t] = g_q[ng * 4096 + p * 64 + t];
    float wr[36];
    #pragma unroll
    for (int u = 0; u < 36; u++) wr[u] = w1c[t * 36 + u];
    float bias = b1c[t], w2a = w2c[t], w2b = w2c[64 + t];
    __syncthreads();
    #pragma unroll
    for (int sy = 0; sy < 2; sy++)
    #pragma unroll
    for (int sx = 0; sx < 2; sx++) {
        float s = bias;
        #pragma unroll
        for (int ky = 0; ky < 6; ky++) {
            int iy = sy * 4 - 1 + ky;
            if (iy < 0 || iy > 7) continue;
            #pragma unroll
            for (int kx = 0; kx < 6; kx++) {
                int ix = sx * 4 - 1 + kx;
                if (ix < 0 || ix > 7) continue;
                s += wr[ky * 6 + kx] * qs3[t][iy * 8 + ix];
            }
        }
        float gl = 0.5f * s * (1.f + erff(s * 0.70710678118654752f));
        contrib[t][(sy * 2 + sx) * 2 + 0] = gl * w2a;
        contrib[t][(sy * 2 + sx) * 2 + 1] = gl * w2b;
    }
    __syncthreads();
    if (t < 8) {
        float s = 0.f;
        for (int cc = 0; cc < 64; cc++) s += contrib[cc][t];
        tmp8[t] = 4.f * tanhf(s);
    }
    __syncthreads();
    if (t < 4) {
        int sy = t >> 1, sx = t & 1;
        g_vs[ng * 8 + t * 2 + 0] = 2.f * ((float)sx + tmp8[t * 2 + 0]) - 1.f;
        g_vs[ng * 8 + t * 2 + 1] = 2.f * ((float)sy + tmp8[t * 2 + 1]) - 1.f;
    }
}

// ---------------- K4: bilinear KV gather + proj. grid 4096 = (ng, which) --------
// dyn smem: wks 64*129 (8256) | xp 128*65 (8320) | kvs 512 -> 17088 fl = 68352 B
__global__ void __launch_bounds__(256) k_kv(
    const float* __restrict__ x, const float* __restrict__ lg,
    const float* __restrict__ lb, const float* __restrict__ wk,
    const float* __restrict__ wv) {
    extern __shared__ float sm[];
    float* wks = sm;
    float* xp  = sm + 8256;
    float* kvs = sm + 16576;
    int bid = blockIdx.x;
    int ng = bid >> 1, which = bid & 1;
    int n = ng >> 3, g = ng & 7;
    int b = n & 63, quad = n >> 6, qh = quad >> 1, qw = quad & 1;
    int t = threadIdx.x;
    const float* wsrc = (which ? wv : wk) + (g << 13);
    #pragma unroll 4
    for (int p = 0; p < 32; p++) {
        int idx = t + (p << 8);
        { int o = idx >> 7, i = idx & 127;
          wks[o * 129 + i] = __ldg(wsrc + idx); }
        { int pos = idx & 63, i = idx >> 6;
          int y = (qh << 3) + (pos >> 3), xx = (qw << 3) + (pos & 7);
          int cc = (g << 7) + i;
          float raw = x[(b * 1024 + cc) * 256 + y * 16 + xx];
          int mid = (b << 8) + y * 16 + xx;
          xp[i * 65 + pos] = (raw - g_mu[mid]) * g_rstd[mid] * __ldg(lg + cc) + __ldg(lb + cc); }
    }
    __syncthreads();
    if (t < 128) {
        #pragma unroll
        for (int j = 0; j < 4; j++) {
            float vx = g_vs[ng * 8 + j * 2], vy = g_vs[ng * 8 + j * 2 + 1];
            float fx = ((vx + 1.f) * 8.f - 1.f) * 0.5f;
            float fy = ((vy + 1.f) * 8.f - 1.f) * 0.5f;
            float x0 = floorf(fx), y0 = floorf(fy);
            float wx1 = fx - x0, wy1 = fy - y0;
            float acc = 0.f;
            #pragma unroll
            for (int dy = 0; dy < 2; dy++)
            #pragma unroll
            for (int dx = 0; dx < 2; dx++) {
                float X = x0 + dx, Y = y0 + dy;
                if (X >= 0.f && X <= 7.f && Y >= 0.f && Y <= 7.f) {
                    float wgt = (dx ? wx1 : 1.f - wx1) * (dy ? wy1 : 1.f - wy1);
                    acc += wgt * xp[t * 65 + (int)Y * 8 + (int)X];
                }
            }
            kvs[t * 4 + j] = acc;
        }
    }
    __syncthreads();
    int o = t & 63, j = t >> 6;
    const float* wrow = wks + o * 129;
    float a = 0.f;
    #pragma unroll 4
    for (int i = 0; i < 128; i++) a += wrow[i] * kvs[i * 4 + j];
    ((which ? g_v : g_k) + (ng << 8))[j * 64 + o] = a;
}

// ---------------- K5: CPB MLP, bf16 mma, barrier-free mainloop ----------------
// 512 thr / 16 warps: wm = w&7 (m0 = wm*32, 2 mt), wn = w>>3 (8 nt = 64 points).
// dyn smem floats: H1p(u32) 128*136 @0 | w1s @17408 | bx @18176 | by @18432 |
// part [2][8][64] @18688 -> 19712 floats = 78848 B
__global__ void __launch_bounds__(512) k_cpb(
    const float* __restrict__ w1, const float* __restrict__ b1,
    const float* __restrict__ b2, const float* __restrict__ w3,
    const float* __restrict__ b3) {
    extern __shared__ float sm[];
    unsigned* H1p = (unsigned*)sm;
    float* w1s = sm + 17408;
    float* bx  = sm + 18176;
    float* by  = sm + 18432;
    float* part = sm + 18688;
    int ng = blockIdx.x, t = threadIdx.x;
    int lane = t & 31, w = t >> 5, gid = lane >> 2, tig = lane & 3;
    if (t < 256) {
        w1s[t] = w1[t]; w1s[256 + t] = w1[256 + t]; w1s[512 + t] = b1[t];
        int qi = t >> 2, j = t & 3;
        float gqx = (2.f / 7.f) * (float)(qi & 7) - 1.f;
        float gqy = (2.f / 7.f) * (float)(qi >> 3) - 1.f;
        float px = gqx - g_vs[ng * 8 + j * 2], py = gqy - g_vs[ng * 8 + j * 2 + 1];
        bx[t] = copysignf(log1pf(fabsf(px)), px);
        by[t] = copysignf(log1pf(fabsf(py)), py);
    }
    int wm = w & 7, wn = w >> 3;
    int m0 = wm << 5;
    float b2a[2], b2b[2], w3r[4];
    b2a[0] = __ldg(b2 + m0 + gid);      b2b[0] = __ldg(b2 + m0 + gid + 8);
    b2a[1] = __ldg(b2 + m0 + 16 + gid); b2b[1] = __ldg(b2 + m0 + 24 + gid);
    w3r[0] = __ldg(w3 + m0 + gid);      w3r[1] = __ldg(w3 + m0 + gid + 8);
    w3r[2] = __ldg(w3 + m0 + 16 + gid); w3r[3] = __ldg(w3 + m0 + 24 + gid);
    float b3v = __ldg(b3);
    __syncthreads();
    for (int np = 0; np < 2; np++) {
        {   // fill H1 (bf16 pairs): rows = hidden-pairs, cols = 128 points
            int col = t & 127, pr0 = (t >> 7) << 5;
            float bxv = bx[np * 128 + col], byv = by[np * 128 + col];
            #pragma unroll 4
            for (int r = 0; r < 32; r++) {
                int pr = pr0 + r;
                float h0 = fmaxf(w1s[2 * pr] * bxv + w1s[256 + 2 * pr] * byv + w1s[512 + 2 * pr], 0.f);
                float h1 = fmaxf(w1s[2 * pr + 1] * bxv + w1s[256 + 2 * pr + 1] * byv + w1s[512 + 2 * pr + 1], 0.f);
                H1p[pr * 136 + col] = pack_bf2(h0, h1);
            }
        }
        __syncthreads();
        float c[2][8][4];
        #pragma unroll
        for (int mt = 0; mt < 2; mt++)
            #pragma unroll
            for (int nt = 0; nt < 8; nt++) {
                c[mt][nt][0] = b2a[mt]; c[mt][nt][1] = b2a[mt];
                c[mt][nt][2] = b2b[mt]; c[mt][nt][3] = b2b[mt];
            }
        unsigned a[2][4];
        #pragma unroll
        for (int mt = 0; mt < 2; mt++) {
            int m = m0 + mt * 16 + gid;
            a[mt][0] = g_w2bf[tig * 256 + m];
            a[mt][1] = g_w2bf[tig * 256 + m + 8];
            a[mt][2] = g_w2bf[(tig + 4) * 256 + m];
            a[mt][3] = g_w2bf[(tig + 4) * 256 + m + 8];
        }
        for (int kc = 0; kc < 16; kc++) {
            unsigned an[2][4];
            if (kc < 15) {
                int k2 = (kc + 1) * 8 + tig;
                #pragma unroll
                for (int mt = 0; mt < 2; mt++) {
                    int m = m0 + mt * 16 + gid;
                    an[mt][0] = g_w2bf[k2 * 256 + m];
                    an[mt][1] = g_w2bf[k2 * 256 + m + 8];
                    an[mt][2] = g_w2bf[(k2 + 4) * 256 + m];
                    an[mt][3] = g_w2bf[(k2 + 4) * 256 + m + 8];
                }
            }
            #pragma unroll
            for (int nt = 0; nt < 8; nt++) {
                int ntg = wn * 8 + nt;
                unsigned b0 = H1p[(kc * 8 + tig) * 136 + ntg * 8 + gid];
                unsigned bv = H1p[(kc * 8 + tig + 4) * 136 + ntg * 8 + gid];
                mma16(c[0][nt], a[0], b0, bv);
                mma16(c[1][nt], a[1], b0, bv);
            }
            if (kc < 15) {
                #pragma unroll
                for (int mt = 0; mt < 2; mt++)
                    #pragma unroll
                    for (int u = 0; u < 4; u++) a[mt][u] = an[mt][u];
            }
        }
        float colsum[16];
        #pragma unroll
        for (int nt = 0; nt < 8; nt++)
            #pragma unroll
            for (int q = 0; q < 2; q++)
                colsum[nt * 2 + q] =
                    w3r[0] * fmaxf(c[0][nt][q], 0.f) + w3r[1] * fmaxf(c[0][nt][2 + q], 0.f) +
                    w3r[2] * fmaxf(c[1][nt][q], 0.f) + w3r[3] * fmaxf(c[1][nt][2 + q], 0.f);
        #pragma unroll
        for (int off = 4; off < 32; off <<= 1)
            #pragma unroll
            for (int i2 = 0; i2 < 16; i2++)
                colsum[i2] += __shfl_xor_sync(0xffffffffu, colsum[i2], off);
        if (gid == 0) {
            #pragma unroll
            for (int i2 = 0; i2 < 16; i2++)
                part[wn * 512 + wm * 64 + (i2 >> 1) * 8 + tig * 2 + (i2 & 1)] = colsum[i2];
        }
        __syncthreads();
        if (t < 128) {
            int wnh = t >> 6, pl = t & 63;
            float s = 0.f;
            #pragma unroll
            for (int wm2 = 0; wm2 < 8; wm2++) s += part[wnh * 512 + wm2 * 64 + pl];
            g_bias[ng * 256 + np * 128 + t] = s + b3v;
        }
        __syncthreads();
    }
}

// ---------------- K6: attention ----------------
__global__ void __launch_bounds__(256) k_att() {
    __shared__ float qs[64][65];
    __shared__ float ks4[4][65], vs4[4][65];
    __shared__ float att_s[64][5];
    int ng = blockIdx.x, n = ng >> 3, g = ng & 7;
    int t = threadIdx.x;
    #pragma unroll
    for (int p = 0; p < 16; p++) {
        int idx = t + (p << 8);
        qs[idx >> 6][idx & 63] = g_q[ng * 4096 + idx];
    }
    { int j = t >> 6, o = t & 63; ks4[j][o] = g_k[(ng << 8) + t]; vs4[j][o] = g_v[(ng << 8) + t]; }
    __syncthreads();
    int qi = t >> 2, j = t & 3;
    float s = 0.f;
    #pragma unroll 8
    for (int d = 0; d < 64; d++) s += qs[d][qi] * ks4[j][d];
    s = s * 0.125f + g_bias[(ng << 8) + t];
    float mx = fmaxf(s, __shfl_xor_sync(0xffffffffu, s, 1));
    mx = fmaxf(mx, __shfl_xor_sync(0xffffffffu, mx, 2));
    float e = __expf(s - mx);
    float sum = e;
    sum += __shfl_xor_sync(0xffffffffu, sum, 1);
    sum += __shfl_xor_sync(0xffffffffu, sum, 2);
    att_s[qi][j] = e / sum;
    __syncthreads();
    int qi2 = t & 63, dg = t >> 6;
    float a0 = att_s[qi2][0], a1 = att_s[qi2][1], a2 = att_s[qi2][2], a3 = att_s[qi2][3];
    #pragma unroll
    for (int dd = 0; dd < 16; dd++) {
        int d = (dg << 4) + dd;
        float r = a0 * vs4[0][d] + a1 * vs4[1][d] + a2 * vs4[2][d] + a3 * vs4[3][d];
        g_att[((g << 6) + d) * 16384 + (n << 6) + qi2] = r;
    }
}

// ---------------- K7: output projection, bf16 2-term split (3 mmas k16) ----------------
__global__ void __launch_bounds__(256) k_out(
    const float* __restrict__ ow, const float* __restrict__ ob,
    float* __restrict__ out) {
    __shared__ unsigned Ah[8 * 136], Am[8 * 136], Bh2[8 * 136], Bm2[8 * 136];
    int blk = blockIdx.x;
    int mb = (blk & 7) << 7, nb = (blk >> 3) << 7;
    int t = threadIdx.x, lane = t & 31, w = t >> 5;
    int gid = lane >> 2, tig = lane & 3;
    int mw = (w >> 2) << 6, nw = (w & 3) << 5;
    float c[4][4][4];
    #pragma unroll
    for (int mt = 0; mt < 4; mt++)
        #pragma unroll
        for (int nt = 0; nt < 4; nt++)
            #pragma unroll
            for (int q = 0; q < 4; q++) c[mt][nt][q] = 0.f;
    int ar = t >> 1, akq = (t & 1) << 3;
    int brp = t >> 5, bcq = (t & 31) << 2;
    for (int ck = 0; ck < 32; ck++) {
        int k0 = ck << 4;
        float4 a0 = *(const float4*)(ow + (mb + ar) * 512 + k0 + akq);
        float4 a1 = *(const float4*)(ow + (mb + ar) * 512 + k0 + akq + 4);
        float4 bb0 = *(const float4*)(g_att + (k0 + 2 * brp) * 16384 + nb + bcq);
        float4 bb1 = *(const float4*)(g_att + (k0 + 2 * brp + 1) * 16384 + nb + bcq);
        __syncthreads();
        {
            float av[8] = {a0.x, a0.y, a0.z, a0.w, a1.x, a1.y, a1.z, a1.w};
            #pragma unroll
            for (int jj = 0; jj < 4; jj++) {
                unsigned short h0, m0v, h1, m1v;
                split_bf(av[jj * 2], h0, m0v);
                split_bf(av[jj * 2 + 1], h1, m1v);
                int p = (akq >> 1) + jj;
                Ah[p * 136 + ar] = (unsigned)h0 | ((unsigned)h1 << 16);
                Am[p * 136 + ar] = (unsigned)m0v | ((unsigned)m1v << 16);
            }
            float bv0[4] = {bb0.x, bb0.y, bb0.z, bb0.w};
            float bv1[4] = {bb1.x, bb1.y, bb1.z, bb1.w};
            #pragma unroll
            for (int jj = 0; jj < 4; jj++) {
                unsigned short h0, m0v, h1, m1v;
                split_bf(bv0[jj], h0, m0v);
                split_bf(bv1[jj], h1, m1v);
                Bh2[brp * 136 + bcq + jj] = (unsigned)h0 | ((unsigned)h1 << 16);
                Bm2[brp * 136 + bcq + jj] = (unsigned)m0v | ((unsigned)m1v << 16);
            }
        }
        __syncthreads();
        unsigned ah[4][4], am[4][4];
        #pragma unroll
        for (int mt = 0; mt < 4; mt++) {
            int m = mw + mt * 16 + gid;
            ah[mt][0] = Ah[tig * 136 + m];       am[mt][0] = Am[tig * 136 + m];
            ah[mt][1] = Ah[tig * 136 + m + 8];   am[mt][1] = Am[tig * 136 + m + 8];
            ah[mt][2] = Ah[(tig + 4) * 136 + m]; am[mt][2] = Am[(tig + 4) * 136 + m];
            ah[mt][3] = Ah[(tig + 4) * 136 + m + 8]; am[mt][3] = Am[(tig + 4) * 136 + m + 8];
        }
        #pragma unroll
        for (int nt = 0; nt < 4; nt++) {
            int col = nw + nt * 8 + gid;
            unsigned bh0 = Bh2[tig * 136 + col], bh1 = Bh2[(tig + 4) * 136 + col];
            unsigned bm0 = Bm2[tig * 136 + col], bm1 = Bm2[(tig + 4) * 136 + col];
            #pragma unroll
            for (int mt = 0; mt < 4; mt++) {
                mma16(c[mt][nt], ah[mt], bh0, bh1);
                mma16(c[mt][nt], am[mt], bh0, bh1);
                mma16(c[mt][nt], ah[mt], bm0, bm1);
            }
        }
    }
    #pragma unroll
    for (int mt = 0; mt < 4; mt++)
        #pragma unroll
        for (int nt = 0; nt < 4; nt++)
            #pragma unroll
            for (int q = 0; q < 4; q++) {
                int o = mb + mw + mt * 16 + gid + ((q >> 1) << 3);
                int col = nb + nw + nt * 8 + tig * 2 + (q & 1);
                int n = col >> 6, qi = col & 63;
                int b = n & 63, quad = n >> 6;
                int y = ((quad >> 1) << 3) + (qi >> 3);
                int xx = ((quad & 1) << 3) + (qi & 7);
                out[((b * 1024 + o) * 16 + y) * 16 + xx] = c[mt][nt][q] + __ldg(ob + o);
            }
}

extern "C" void kernel_launch(void* const* d_in, const int* in_sizes, int n_in,
                              void* d_out, int out_size) {
    const float* x      = (const float*)d_in[0];
    const float* ln_g   = (const float*)d_in[1];
    const float* ln_b   = (const float*)d_in[2];
    const float* wq     = (const float*)d_in[3];
    const float* wk     = (const float*)d_in[4];
    const float* wv     = (const float*)d_in[5];
    const float* off_w1 = (const float*)d_in[6];
    const float* off_b1 = (const float*)d_in[7];
    const float* off_w2 = (const float*)d_in[8];
    const float* cpb_w1 = (const float*)d_in[9];
    const float* cpb_b1 = (const float*)d_in[10];
    const float* cpb_w2 = (const float*)d_in[11];
    const float* cpb_b2 = (const float*)d_in[12];
    const float* cpb_w3 = (const float*)d_in[13];
    const float* cpb_b3 = (const float*)d_in[14];
    const float* out_w  = (const float*)d_in[15];
    const float* out_b  = (const float*)d_in[16];
    float* out = (float*)d_out;
    const int QP_SMEM  = 16448 * 4;   // 65792 B
    const int KV_SMEM  = 17088 * 4;   // 68352 B
    const int CPB_SMEM = 19712 * 4;   // 78848 B
    cudaFuncSetAttribute(k_qproj, cudaFuncAttributeMaxDynamicSharedMemorySize, QP_SMEM);
    cudaFuncSetAttribute(k_kv,  cudaFuncAttributeMaxDynamicSharedMemorySize, KV_SMEM);
    cudaFuncSetAttribute(k_cpb, cudaFuncAttributeMaxDynamicSharedMemorySize, CPB_SMEM);
    k_prep<<<128, 256>>>(cpb_w2);
    k_ln<<<512, 256>>>(x);
    k_qproj<<<2048, 256, QP_SMEM>>>(x, ln_g, ln_b, wq);
    k_off<<<2048, 64>>>(off_w1, off_b1, off_w2);
    k_kv<<<4096, 256, KV_SMEM>>>(x, ln_g, ln_b, wk, wv);
    k_cpb<<<2048, 512, CPB_SMEM>>>(cpb_w1, cpb_b1, cpb_b2, cpb_w3, cpb_b3);
    k_att<<<2048, 256>>>();
    k_out<<<1024, 256>>>(out_w, out_b, out);
}